// round 4
// baseline (speedup 1.0000x reference)
#include <cuda_runtime.h>
#include <math_constants.h>

// StratifiedMaxPooling: out[b,c] = max_{j: labels[j]==c} values[b,j]
// values: [B=128, N=200000] f32, labels: [N] int32, C=100.
//
// R4: transpose-staged conflict-free scatter.
//  - Tile = 32 columns x 128 rows staged in smem (padded, conflict-free).
//  - Process phase: warp(rb,g): lane = row; all lanes of a warp handle the
//    SAME column => same class => distinct acc addresses (row-major, pitch
//    101, gcd(101,32)=1 => conflict-free). No rounds/REDUX/atomics.
//  - Cross-warp same-class races eliminated by grouping columns by their
//    match_any leader lane: group = leader>>2; warp g processes only its
//    group's columns, so equal-label columns always share a warp.
//  - LDG prefetch of tile t+1 overlaps processing of tile t.
//  - Single kernel: unsigned ordered keys (ukey(finite) > 0) make the
//    statically-zeroed g_keys valid without an init kernel; last block
//    (atomic counter) decodes to d_out and self-resets for graph replays.

#define FULL 0xFFFFFFFFu

static const int GRID_N  = 148;    // one block per SM
static const int NTHR    = 1024;   // 32 warps
static const int C_NUM   = 100;
static const int C_PAD   = 101;    // acc pitch (gcd with 32 == 1)
static const int B_NUM   = 128;
static const int NOUT    = B_NUM * C_NUM;     // 12800
static const int TILE    = 32;
static const int SPITCH  = 129;    // stage pitch (gcd with 32 == 1)

__device__ unsigned g_keys[NOUT];   // zero static init; self-cleaning
__device__ unsigned g_done;         // zero static init; self-cleaning

// Monotonic float -> unsigned key. ukey of any FINITE float is >= 0x00800000
// > 0, so 0 acts as "empty" identity for atomicMax.
__device__ __forceinline__ unsigned ukey(float f) {
    int x = __float_as_int(f);
    return (unsigned)(x ^ ((x >> 31) | 0x80000000));
}
__device__ __forceinline__ float udecode(unsigned u) {
    unsigned m = ((int)u < 0) ? 0x80000000u : 0xFFFFFFFFu;
    return __int_as_float((int)(u ^ m));
}

__global__ __launch_bounds__(NTHR, 1)
void pool_kernel(const float* __restrict__ values,
                 const int*   __restrict__ labels,
                 float* __restrict__ out, int N)
{
    __shared__ float    stage[TILE * SPITCH];   // [col][row], 16.5 KB
    __shared__ float    acc[B_NUM * C_PAD];     // [row][class], 51.7 KB
    __shared__ unsigned s_last;

    const int tid  = threadIdx.x;
    const int lane = tid & 31;
    const int warp = tid >> 5;

    for (int i = tid; i < B_NUM * C_PAD; i += NTHR) acc[i] = -CUDART_INF_F;

    // ---- load mapping: thread -> (row, 4-col quad) of the tile
    const int lrow  = tid >> 3;                  // 0..127
    const int lcolq = tid & 7;                   // quad 0..7
    const size_t vbase = (size_t)lrow * N + 4 * lcolq;
    float* const st0 = &stage[(4 * lcolq) * SPITCH + lrow];

    // ---- process mapping: warp -> (row block, column group)
    const int rb   = warp & 3;                   // row block 0..3
    const int gw   = warp >> 2;                  // column group 0..7
    const int rowl = rb * 32 + lane;             // my row
    float* const accrow = &acc[rowl * C_PAD];
    const float* const strow = &stage[rowl];

    const int ntiles = N / TILE;

    // ---- prologue: fetch tile t0
    int t = blockIdx.x;
    float4 v = make_float4(0.f, 0.f, 0.f, 0.f);
    int cl = 0;
    if (t < ntiles) {
        v  = *reinterpret_cast<const float4*>(values + vbase + (size_t)t * TILE);
        cl = labels[t * TILE + lane];
    }
    __syncthreads();                  // acc init done
    if (t < ntiles) {
        st0[0 * SPITCH] = v.x;
        st0[1 * SPITCH] = v.y;
        st0[2 * SPITCH] = v.z;
        st0[3 * SPITCH] = v.w;
    }
    __syncthreads();                  // stage(t) ready

    while (t < ntiles) {
        const int tn = t + GRID_N;
        const bool haven = tn < ntiles;
        float4 vn = make_float4(0.f, 0.f, 0.f, 0.f);
        int cln = 0;
        if (haven) {                  // prefetch next tile (overlaps process)
            vn  = *reinterpret_cast<const float4*>(values + vbase + (size_t)tn * TILE);
            cln = labels[tn * TILE + lane];
        }

        // ---- process tile t from stage
        {
            const unsigned mm = __match_any_sync(FULL, cl);
            const int leader  = __ffs(mm) - 1;
            unsigned mask = __ballot_sync(FULL, (leader >> 2) == gw);
            while (mask) {
                const int col = __ffs(mask) - 1;
                mask &= mask - 1;
                const int cc = __shfl_sync(FULL, cl, col);
                const float sv = strow[col * SPITCH];
                accrow[cc] = fmaxf(accrow[cc], sv);
            }
        }

        __syncthreads();              // all reads of stage(t) done
        if (haven) {
            st0[0 * SPITCH] = vn.x;
            st0[1 * SPITCH] = vn.y;
            st0[2 * SPITCH] = vn.z;
            st0[3 * SPITCH] = vn.w;
        }
        __syncthreads();              // stage(t+GRID) ready
        t = tn; cl = cln;
    }

    // ---- remainder columns (N % 32), handled by block 0 via global atomics
    const int remstart = ntiles * TILE;
    const int rem = N - remstart;
    if (rem > 0 && blockIdx.x == 0) {
        for (int i = tid; i < rem * B_NUM; i += NTHR) {
            const int r = i / rem;
            const int j = remstart + (i - r * rem);
            const int c = labels[j];
            atomicMax(&g_keys[r * C_NUM + c], ukey(values[(size_t)r * N + j]));
        }
    }

    // ---- flush block partials
    for (int i = tid; i < NOUT; i += NTHR) {
        const int r = (int)(((unsigned)i * 5243u) >> 19);   // i / 100
        const int c = i - r * C_NUM;
        atomicMax(&g_keys[i], ukey(acc[r * C_PAD + c]));
    }
    __threadfence();
    __syncthreads();
    if (tid == 0)
        s_last = (atomicAdd(&g_done, 1u) == (unsigned)(gridDim.x - 1));
    __syncthreads();

    // ---- last block: decode to output, self-reset for next graph replay
    if (s_last) {
        for (int i = tid; i < NOUT; i += NTHR) {
            const unsigned u = __ldcg(&g_keys[i]);
            out[i] = udecode(u);
            g_keys[i] = 0u;
        }
        if (tid == 0) g_done = 0u;
    }
}

extern "C" void kernel_launch(void* const* d_in, const int* in_sizes, int n_in,
                              void* d_out, int out_size)
{
    const float* values = (const float*)d_in[0];
    const int*   labels = (const int*)d_in[1];
    const int N = in_sizes[1];   // 200000

    pool_kernel<<<GRID_N, NTHR>>>(values, labels, (float*)d_out, N);
}

// round 7
// speedup vs baseline: 1.3807x; 1.3807x over previous
#include <cuda_runtime.h>
#include <math_constants.h>

// StratifiedMaxPooling: out[b,c] = max_{j: labels[j]==c} values[b,j]
// values: [B=128, N=200000] f32, labels: [N] int32, C=100.
//
// R5: transpose-staged conflict-free scatter, latency-optimized.
//  - 2 blocks/SM (512 thr), each owns 64 rows: independent blocks interleave
//    so schedulers always have issuable warps despite per-block barriers.
//  - Double-buffered 32-col x 64-row stage -> ONE __syncthreads per tile.
//  - Process: warp (rb, gw): lane = row; whole warp handles one column =>
//    one class => distinct acc addresses (pitch 101, gcd(101,32)=1: no bank
//    conflicts). Cross-warp same-class races killed by leader grouping with
//    group = leader&7 (balanced, low-lane leader bias spread evenly).
//  - Single kernel: unsigned keys make zero-initialized g_keys valid with no
//    init kernel; last block decodes and self-resets for graph replay.

#define FULL 0xFFFFFFFFu

static const int NTHR    = 512;    // 16 warps
static const int ROWS_PB = 64;     // rows per block (B split in halves)
static const int C_NUM   = 100;
static const int C_PAD   = 101;    // acc pitch, gcd(101,32)=1
static const int NOUT    = 128 * C_NUM;   // 12800
static const int TILE    = 32;     // columns per tile
static const int RPITCH  = 65;     // stage row pitch, gcd(65,32)=1
static const int NSTREAM = 148;    // tile stride (grid = 2*NSTREAM)

__device__ unsigned g_keys[NOUT];  // zero static init; self-cleaning
__device__ unsigned g_done;        // zero static init; self-cleaning

// Monotonic float -> unsigned key; ukey(any finite or -inf) > 0, so 0 is a
// valid "empty" identity for atomicMax.
__device__ __forceinline__ unsigned ukey(float f) {
    int x = __float_as_int(f);
    return (unsigned)(x ^ ((x >> 31) | 0x80000000));
}
__device__ __forceinline__ float udecode(unsigned u) {
    unsigned m = ((int)u < 0) ? 0x80000000u : 0xFFFFFFFFu;
    return __int_as_float((int)(u ^ m));
}

__global__ __launch_bounds__(NTHR, 2)
void pool_kernel(const float* __restrict__ values,
                 const int*   __restrict__ labels,
                 float* __restrict__ out, int N, int ntiles)
{
    __shared__ float    stage[2][TILE * RPITCH];  // [buf][col][row] 16.6 KB
    __shared__ int      scl[2][TILE];             // staged labels
    __shared__ float    acc[ROWS_PB * C_PAD];     // [row][class]   25.9 KB
    __shared__ int      s_last;

    const int tid  = threadIdx.x;
    const int lane = tid & 31;
    const int warp = tid >> 5;
    const int half = blockIdx.x & 1;       // which 64-row half of B
    const int strm = blockIdx.x >> 1;      // tile stream start

    for (int i = tid; i < ROWS_PB * C_PAD; i += NTHR) acc[i] = -CUDART_INF_F;

    // load mapping: thread -> (row, 4-col quad); warp = 4 rows x 128B, coalesced
    const int lrow  = tid >> 3;            // 0..63
    const int lcolq = tid & 7;             // 0..7
    const float* const vbase =
        values + (size_t)(half * ROWS_PB + lrow) * N + 4 * lcolq;
    const int soff = (4 * lcolq) * RPITCH + lrow;

    // process mapping: warp -> (row block, column group)
    const int rb = warp >> 3;              // 0..1
    const int gw = warp & 7;               // 0..7
    const int rowl = rb * 32 + lane;
    float* const accrow = &acc[rowl * C_PAD];
    const float* const strow0 = &stage[0][rowl];
    const float* const strow1 = &stage[1][rowl];

    // ---- prologue: stage tile t0 into buf0; prefetch t0+NSTREAM into regs
    int t = strm;
    {
        if (t < ntiles) {
            float4 v0 = *reinterpret_cast<const float4*>(vbase + (size_t)t * TILE);
            float* s0 = &stage[0][soff];
            s0[0] = v0.x; s0[RPITCH] = v0.y;
            s0[2 * RPITCH] = v0.z; s0[3 * RPITCH] = v0.w;
            if (tid < TILE) scl[0][tid] = labels[t * TILE + tid];
        }
    }
    int   t1 = t + NSTREAM;
    bool  h1 = t1 < ntiles;
    float4 v1 = make_float4(0.f, 0.f, 0.f, 0.f);
    int    l1 = 0;
    if (h1) {
        v1 = *reinterpret_cast<const float4*>(vbase + (size_t)t1 * TILE);
        if (tid < TILE) l1 = labels[t1 * TILE + tid];
    }
    __syncthreads();   // buf0 + acc ready

    int p = 0;
    for (; t < ntiles; t += NSTREAM) {
        // store tile t+NSTREAM (regs) into buf 1-p
        if (h1) {
            float* s1 = &stage[1 - p][soff];
            s1[0] = v1.x; s1[RPITCH] = v1.y;
            s1[2 * RPITCH] = v1.z; s1[3 * RPITCH] = v1.w;
            if (tid < TILE) scl[1 - p][tid] = l1;
        }
        // prefetch tile t+2*NSTREAM into regs (overlaps process below)
        const int t2 = t + 2 * NSTREAM;
        const bool h2 = t2 < ntiles;
        if (h2) {
            v1 = *reinterpret_cast<const float4*>(vbase + (size_t)t2 * TILE);
            if (tid < TILE) l1 = labels[t2 * TILE + tid];
        }
        h1 = h2;

        // process tile t from buf p
        {
            const int cls = scl[p][lane];
            const unsigned mm = __match_any_sync(FULL, cls);
            const int leader  = __ffs((int)mm) - 1;
            unsigned mask = __ballot_sync(FULL, (leader & 7) == gw);
            const float* const sv = p ? strow1 : strow0;
            while (mask) {
                const int col = __ffs((int)mask) - 1;
                mask &= mask - 1;
                const int cc = __shfl_sync(FULL, cls, col);
                const float x = sv[col * RPITCH];
                accrow[cc] = fmaxf(accrow[cc], x);
            }
        }
        __syncthreads();   // buf 1-p stores done; buf p reads done
        p ^= 1;
    }

    // ---- remainder columns (N % 32): stream 0 blocks handle their rows
    const int remstart = ntiles * TILE;
    if (remstart < N && strm == 0) {
        const int rem = N - remstart;
        for (int i = tid; i < rem * ROWS_PB; i += NTHR) {
            const int r = i / rem;
            const int j = remstart + (i - r * rem);
            const int grow = half * ROWS_PB + r;
            const int c = labels[j];
            atomicMax(&g_keys[grow * C_NUM + c],
                      ukey(values[(size_t)grow * N + j]));
        }
    }

    // ---- flush block partials (acc writes all visible: loop's last barrier)
    for (int i = tid; i < ROWS_PB * C_NUM; i += NTHR) {
        const int r = i / C_NUM;
        const int c = i - r * C_NUM;
        atomicMax(&g_keys[(half * ROWS_PB + r) * C_NUM + c],
                  ukey(acc[r * C_PAD + c]));
    }
    __threadfence();
    __syncthreads();
    if (tid == 0)
        s_last = (atomicAdd(&g_done, 1u) == (unsigned)(gridDim.x - 1));
    __syncthreads();

    // ---- last block: decode to output, self-reset for graph replays
    if (s_last) {
        for (int i = tid; i < NOUT; i += NTHR) {
            out[i] = udecode(__ldcg(&g_keys[i]));
            g_keys[i] = 0u;
        }
        __threadfence();
        if (tid == 0) g_done = 0u;
    }
}

extern "C" void kernel_launch(void* const* d_in, const int* in_sizes, int n_in,
                              void* d_out, int out_size)
{
    const float* values = (const float*)d_in[0];
    const int*   labels = (const int*)d_in[1];
    const int N = in_sizes[1];        // 200000
    const int ntiles = N / TILE;      // 6250

    pool_kernel<<<2 * NSTREAM, NTHR>>>(values, labels, (float*)d_out, N, ntiles);
}

// round 8
// speedup vs baseline: 2.0764x; 1.5039x over previous
#include <cuda_runtime.h>
#include <math_constants.h>

// StratifiedMaxPooling: out[b,c] = max_{j: labels[j]==c} values[b,j]
// values: [B=128, N=200000] f32, labels: [N] int32, C=100.
//
// R8: transpose-staged conflict-free scatter, v3.
//  - 2 blocks/SM (512 thr), each owns 64 rows.
//  - TILE=64 columns, double-buffered stage, ONE barrier per tile.
//  - Grouping by class: warp g processes columns with (class & 15) == g.
//    Equal-label columns land in the same warp by construction (no match_any
//    / leader math). Each lane covers rows {lane, lane+32}: all scatter
//    addresses within a warp are distinct except repeats of the same class,
//    which are written by the SAME lane => thread-ordered, race-free.
//  - Inner loop unrolled x2 columns => 8 independent LDS batched per iter.
//  - Bank-conflict-free: stage pitch 65 ((col+lane)%32 distinct),
//    acc pitch 101 ((5*lane+c)%32 distinct, 5 invertible mod 32).
//  - Single kernel: unsigned keys make zero-initialized g_keys a valid
//    identity; last block decodes to out and self-resets for graph replay.

#define FULL 0xFFFFFFFFu

static const int NTHR    = 512;    // 16 warps
static const int ROWS_PB = 64;     // rows per block
static const int C_NUM   = 100;
static const int C_PAD   = 101;    // acc pitch
static const int NOUT    = 128 * C_NUM;   // 12800
static const int TILE    = 64;     // columns per tile
static const int RPITCH  = 65;     // stage row pitch
static const int NSTREAM = 148;    // tile stride (grid = 2*NSTREAM)

__device__ unsigned g_keys[NOUT];  // zero static init; self-cleaning
__device__ unsigned g_done;        // zero static init; self-cleaning

__device__ __forceinline__ unsigned ukey(float f) {
    int x = __float_as_int(f);
    return (unsigned)(x ^ ((x >> 31) | 0x80000000));
}
__device__ __forceinline__ float udecode(unsigned u) {
    unsigned m = ((int)u < 0) ? 0x80000000u : 0xFFFFFFFFu;
    return __int_as_float((int)(u ^ m));
}

__global__ __launch_bounds__(NTHR, 2)
void pool_kernel(const float* __restrict__ values,
                 const int*   __restrict__ labels,
                 float* __restrict__ out, int N, int ntiles)
{
    __shared__ float stage[2][TILE * RPITCH];  // 2 x 16.6 KB
    __shared__ int   scl[2][TILE];
    __shared__ float acc[ROWS_PB * C_PAD];     // 25.9 KB
    __shared__ int   s_last;

    const int tid  = threadIdx.x;
    const int lane = tid & 31;
    const int warp = tid >> 5;                 // == column group id (0..15)
    const int half = blockIdx.x & 1;
    const int strm = blockIdx.x >> 1;

    for (int i = tid; i < ROWS_PB * C_PAD; i += NTHR) acc[i] = -CUDART_INF_F;

    // ---- load mapping: thread -> row (tid>>3), two 4-col quads (q, q+8)
    const int lrow = tid >> 3;
    const int q    = tid & 7;
    const float* const vrow = values + (size_t)(half * ROWS_PB + lrow) * N;
    const int cqa = 4 * q;             // cols cqa..cqa+3
    const int cqb = 4 * (q + 8);       // cols cqb..cqb+3
    const int sofa = cqa * RPITCH + lrow;
    const int sofb = cqb * RPITCH + lrow;

    // ---- process mapping
    float* const accA = acc + lane * C_PAD;
    float* const accB = acc + (lane + 32) * C_PAD;

    // ---- prologue: stage tile t0 into buf0; prefetch t0+NSTREAM into regs
    int t = strm;
    if (t < ntiles) {
        const float* vt = vrow + (size_t)t * TILE;
        float4 a = __ldcs(reinterpret_cast<const float4*>(vt + cqa));
        float4 b = __ldcs(reinterpret_cast<const float4*>(vt + cqb));
        float* sa = &stage[0][sofa];
        float* sb = &stage[0][sofb];
        sa[0] = a.x; sa[RPITCH] = a.y; sa[2*RPITCH] = a.z; sa[3*RPITCH] = a.w;
        sb[0] = b.x; sb[RPITCH] = b.y; sb[2*RPITCH] = b.z; sb[3*RPITCH] = b.w;
        if (tid < TILE) scl[0][tid] = labels[t * TILE + tid];
    }
    int    t1 = t + NSTREAM;
    bool   h1 = t1 < ntiles;
    float4 va = make_float4(0.f,0.f,0.f,0.f), vb = va;
    int    l1 = 0;
    if (h1) {
        const float* vt = vrow + (size_t)t1 * TILE;
        va = __ldcs(reinterpret_cast<const float4*>(vt + cqa));
        vb = __ldcs(reinterpret_cast<const float4*>(vt + cqb));
        if (tid < TILE) l1 = labels[t1 * TILE + tid];
    }
    __syncthreads();   // buf0 + acc ready

    int p = 0;
    for (; t < ntiles; t += NSTREAM) {
        // store prefetched tile into buf 1-p
        if (h1) {
            float* sa = &stage[1 - p][sofa];
            float* sb = &stage[1 - p][sofb];
            sa[0]=va.x; sa[RPITCH]=va.y; sa[2*RPITCH]=va.z; sa[3*RPITCH]=va.w;
            sb[0]=vb.x; sb[RPITCH]=vb.y; sb[2*RPITCH]=vb.z; sb[3*RPITCH]=vb.w;
            if (tid < TILE) scl[1 - p][tid] = l1;
        }
        // prefetch t+2*NSTREAM (overlaps processing below)
        const int t2 = t + 2 * NSTREAM;
        const bool h2 = t2 < ntiles;
        if (h2) {
            const float* vt = vrow + (size_t)t2 * TILE;
            va = __ldcs(reinterpret_cast<const float4*>(vt + cqa));
            vb = __ldcs(reinterpret_cast<const float4*>(vt + cqb));
            if (tid < TILE) l1 = labels[t2 * TILE + tid];
        }
        h1 = h2;

        // ---- process tile t from buf p: two 32-column sub-tiles
        const float* const stg = stage[p];
#pragma unroll
        for (int sub = 0; sub < 2; sub++) {
            const int cls = scl[p][sub * 32 + lane];
            unsigned mask = __ballot_sync(FULL, (cls & 15) == warp);
            const float* const sbase = stg + (sub * 32) * RPITCH;
            while (mask) {
                const int c0 = __ffs((int)mask) - 1; mask &= mask - 1;
                int c1 = c0;
                if (mask) { c1 = __ffs((int)mask) - 1; mask &= mask - 1; }
                const int k0 = __shfl_sync(FULL, cls, c0);
                const int k1 = __shfl_sync(FULL, cls, c1);
                const float* s0 = sbase + c0 * RPITCH;
                const float* s1 = sbase + c1 * RPITCH;
                const float x0a = s0[lane], x0b = s0[lane + 32];
                const float x1a = s1[lane], x1b = s1[lane + 32];
                float* p0a = accA + k0;  float* p0b = accB + k0;
                float* p1a = accA + k1;  float* p1b = accB + k1;
                // c1==c0 repeat is same-lane => thread-ordered, still correct
                *p0a = fmaxf(*p0a, x0a);
                *p0b = fmaxf(*p0b, x0b);
                *p1a = fmaxf(*p1a, x1a);
                *p1b = fmaxf(*p1b, x1b);
            }
        }
        __syncthreads();   // buf 1-p stores done; buf p reads done
        p ^= 1;
    }

    // ---- remainder columns (N % 64), generic guard (zero cost when 0)
    const int remstart = ntiles * TILE;
    if (remstart < N && strm == 0) {
        const int rem = N - remstart;
        for (int i = tid; i < rem * ROWS_PB; i += NTHR) {
            const int r = i / rem;
            const int j = remstart + (i - r * rem);
            const int grow = half * ROWS_PB + r;
            atomicMax(&g_keys[grow * C_NUM + labels[j]],
                      ukey(values[(size_t)grow * N + j]));
        }
    }

    // ---- flush block partials (final loop barrier makes acc visible)
    for (int i = tid; i < ROWS_PB * C_NUM; i += NTHR) {
        const int r = i / C_NUM;
        const int c = i - r * C_NUM;
        atomicMax(&g_keys[(half * ROWS_PB + r) * C_NUM + c],
                  ukey(acc[r * C_PAD + c]));
    }
    __threadfence();
    __syncthreads();
    if (tid == 0)
        s_last = (atomicAdd(&g_done, 1u) == (unsigned)(gridDim.x - 1));
    __syncthreads();

    // ---- last block: decode to output, self-reset for graph replays
    if (s_last) {
        for (int i = tid; i < NOUT; i += NTHR) {
            out[i] = udecode(__ldcg(&g_keys[i]));
            g_keys[i] = 0u;
        }
        __threadfence();
        if (tid == 0) g_done = 0u;
    }
}

extern "C" void kernel_launch(void* const* d_in, const int* in_sizes, int n_in,
                              void* d_out, int out_size)
{
    const float* values = (const float*)d_in[0];
    const int*   labels = (const int*)d_in[1];
    const int N = in_sizes[1];        // 200000
    const int ntiles = N / TILE;      // 3125

    pool_kernel<<<2 * NSTREAM, NTHR>>>(values, labels, (float*)d_out, N, ntiles);
}